// round 7
// baseline (speedup 1.0000x reference)
#include <cuda_runtime.h>
#include <cstdint>

// Problem constants
#define N_NODES 2048
#define NF4     512             // N_NODES/4 float4 columns
#define K_TOTAL 3072            // B*L
#define KC      96              // k rows per block (chunk)
#define NKC     32              // chunks (KC*NKC == K_TOTAL)
#define NBN     8               // n blocks (64 f4 cols each)
#define SROWS   8               // rows per cp.async stage
#define NSTG    (KC / SROWS)    // 12 stages per chunk
#define ROWS    3072

// Scratch device globals (no allocation allowed). Fully overwritten each launch.
__device__ float g_part[NKC * 8 * N_NODES];   // 2 MB partial conv sums
__device__ float g_per_node[N_NODES];         // 8 KB per-node scalars

// ---- helpers ---------------------------------------------------------------
__device__ __forceinline__ unsigned smem_u32(const void* p) {
    unsigned a;
    asm("{ .reg .u64 t; cvta.to.shared.u64 t, %1; cvt.u32.u64 %0, t; }"
        : "=r"(a) : "l"(p));
    return a;
}
__device__ __forceinline__ void cp16(void* sdst, const void* gsrc) {
    unsigned d = smem_u32(sdst);
    asm volatile("cp.async.cg.shared.global [%0], [%1], 16;"
                 :: "r"(d), "l"(gsrc) : "memory");
}
__device__ __forceinline__ void cp_commit() {
    asm volatile("cp.async.commit_group;" ::: "memory");
}
__device__ __forceinline__ void cp_wait2() {
    asm volatile("cp.async.wait_group 2;" ::: "memory");
}
__device__ __forceinline__ unsigned long long pack2(float a, float b) {
    unsigned long long r;
    asm("mov.b64 %0, {%1, %2};" : "=l"(r) : "f"(a), "f"(b));
    return r;
}
__device__ __forceinline__ void fma2n(unsigned long long& d,
                                      unsigned long long a,
                                      unsigned long long b) {
    asm("fma.rn.f32x2 %0, %1, %2, %0;" : "+l"(d) : "l"(a), "l"(b));
}
__device__ __forceinline__ void unpack2(unsigned long long v, float& a, float& b) {
    asm("mov.b64 {%0, %1}, %2;" : "=f"(a), "=f"(b) : "l"(v));
}
__device__ __forceinline__ float ldg1v(const float* p) {
    float v;
    asm volatile("ld.global.nc.f32 %0, [%1];" : "=f"(v) : "l"(p));
    return v;
}

// ---------------------------------------------------------------------------
// K1: partial skinny GEMM with cp.async staging.
// Block = 64 f4-cols x KC=96 rows, pipelined in 12 stages of 8 rows (8KB),
// 3-stage SMEM ring. Thread (ln = tid&63, q = tid>>6) consumes 2 rows/stage.
// The cross-quarter reduction buffer ALIASES the staging ring (dead after the
// mainloop) to stay under the 48KB static smem cap: total 30KB.
// grid = (8, 32) x 256 threads, 3 CTAs/SM.
// ---------------------------------------------------------------------------
__global__ __launch_bounds__(256, 3) void k_gemm_partial(
    const float4* __restrict__ x4, const float* __restrict__ Wc)
{
    __shared__ alignas(16) char smem_raw[3 * SROWS * 64 * 16];  // 24 KB ring
    __shared__ alignas(16) float sWd[KC * 16];                  // 6 KB weights

    float4 (*sx)[SROWS * 64] = reinterpret_cast<float4 (*)[SROWS * 64]>(smem_raw);
    float4 (*sred)[64][8]    = reinterpret_cast<float4 (*)[64][8]>(smem_raw);

    const int tid  = threadIdx.x;
    const int ln   = tid & 63;
    const int q    = tid >> 6;
    const int nblk = blockIdx.x;                       // 0..7
    const int kblk = blockIdx.y;                       // 0..31
    const int k0   = kblk * KC;

    const float4* xbase = x4 + (size_t)k0 * NF4 + nblk * 64;

    // stage Wc chunk, duplicated into f32x2 pairs
    const float* wsrc = Wc + (size_t)k0 * 8;
    #pragma unroll
    for (int i = tid; i < KC * 16; i += 256) sWd[i] = wsrc[i >> 1];

    // prologue: stages 0,1 in flight
    #pragma unroll
    for (int s = 0; s < 2; s++) {
        #pragma unroll
        for (int t = 0; t < 2; t++) {
            int idx = tid + t * 256;                   // f4 index in stage
            int row = idx >> 6, col = idx & 63;
            cp16(&sx[s][idx], xbase + ((size_t)s * SROWS + row) * NF4 + col);
        }
        cp_commit();
    }

    unsigned long long accp[2][8];
    #pragma unroll
    for (int p = 0; p < 2; p++)
        #pragma unroll
        for (int j = 0; j < 8; j++) accp[p][j] = 0ull;

    const ulonglong2* wp = reinterpret_cast<const ulonglong2*>(sWd);

    #pragma unroll
    for (int s = 0; s < NSTG; s++) {
        if (s + 2 < NSTG) {                            // issue stage s+2
            #pragma unroll
            for (int t = 0; t < 2; t++) {
                int idx = tid + t * 256;
                int row = idx >> 6, col = idx & 63;
                cp16(&sx[(s + 2) % 3][idx],
                     xbase + ((size_t)(s + 2) * SROWS + row) * NF4 + col);
            }
        }
        cp_commit();                                   // always: keeps count invariant
        cp_wait2();                                    // stage s complete
        __syncthreads();

        #pragma unroll
        for (int rr = 0; rr < 2; rr++) {               // consume 2 rows
            const int row = q * 2 + rr;
            float4 xv = sx[s % 3][row * 64 + ln];
            unsigned long long lo = pack2(xv.x, xv.y);
            unsigned long long hi = pack2(xv.z, xv.w);
            const ulonglong2* w = wp + (size_t)(s * SROWS + row) * 4;
            #pragma unroll
            for (int jj = 0; jj < 4; jj++) {
                ulonglong2 wv = w[jj];                 // broadcast LDS.128
                fma2n(accp[0][2 * jj],     lo, wv.x);
                fma2n(accp[1][2 * jj],     hi, wv.x);
                fma2n(accp[0][2 * jj + 1], lo, wv.y);
                fma2n(accp[1][2 * jj + 1], hi, wv.y);
            }
        }
        __syncthreads();                               // protect ring reuse
    }

    // Ring is dead now; reuse it as the cross-quarter reduction buffer.
    if (q != 0) {
        #pragma unroll
        for (int j = 0; j < 8; j++) {
            float4 o;
            unpack2(accp[0][j], o.x, o.y);
            unpack2(accp[1][j], o.z, o.w);
            sred[q - 1][ln][j] = o;
        }
    }
    __syncthreads();
    if (q == 0) {
        float4* gp4 = reinterpret_cast<float4*>(g_part);
        #pragma unroll
        for (int j = 0; j < 8; j++) {
            float4 o;
            unpack2(accp[0][j], o.x, o.y);
            unpack2(accp[1][j], o.z, o.w);
            #pragma unroll
            for (int sIdx = 0; sIdx < 3; sIdx++) {
                float4 r = sred[sIdx][ln][j];
                o.x += r.x; o.y += r.y; o.z += r.z; o.w += r.w;
            }
            gp4[(size_t)(kblk * 8 + j) * NF4 + nblk * 64 + ln] = o;
        }
    }
}

// ---------------------------------------------------------------------------
// K2: reduce 32 partials per (n,j), add bc, folded MLP, write per_node[n].
// grid = 32 x 256; block = 64 nodes x 4 k-slices (8 chunks each).
// ---------------------------------------------------------------------------
__global__ __launch_bounds__(256) void k_reduce_mlp(
    const float* __restrict__ bc, const float* __restrict__ W1,
    const float* __restrict__ b1, const float* __restrict__ W2,
    const float* __restrict__ b2)
{
    __shared__ float sWeff[256];
    __shared__ float sb1[32];
    __shared__ float sW2v[32];
    __shared__ float sred[3 * 64 * 9];

    const int tid = threadIdx.x;
    const int ln  = tid & 63;
    const int q   = tid >> 6;
    const int n   = blockIdx.x * 64 + ln;

    sWeff[tid] = W1[tid] + W1[tid + 256];
    if (tid < 32) { sb1[tid] = b1[tid]; sW2v[tid] = W2[tid]; }

    float conv[8];
    #pragma unroll
    for (int j = 0; j < 8; j++) conv[j] = 0.0f;

    const int kc0 = q * 8;
    #pragma unroll
    for (int kc = kc0; kc < kc0 + 8; kc++) {
        const float* p = g_part + (size_t)(kc * 8) * N_NODES + n;
        float v[8];
        #pragma unroll
        for (int j = 0; j < 8; j++)
            v[j] = ldg1v(p + (size_t)j * N_NODES);
        #pragma unroll
        for (int j = 0; j < 8; j++) conv[j] += v[j];
    }

    if (q != 0) {
        #pragma unroll
        for (int j = 0; j < 8; j++)
            sred[(size_t)(q - 1) * 64 * 9 + ln * 9 + j] = conv[j];
    }
    __syncthreads();
    if (q == 0) {
        #pragma unroll
        for (int j = 0; j < 8; j++) {
            #pragma unroll
            for (int s = 0; s < 3; s++)
                conv[j] += sred[(size_t)s * 64 * 9 + ln * 9 + j];
            conv[j] += __ldg(bc + j);
        }

        float pn = __ldg(b2);
        #pragma unroll 4
        for (int m = 0; m < 32; m++) {
            float h = sb1[m];
            #pragma unroll
            for (int j = 0; j < 8; j++)
                h = fmaf(conv[j], sWeff[j * 32 + m], h);
            h = fmaxf(h, 0.01f * h);    // leaky_relu
            pn = fmaf(h, sW2v[m], pn);
        }
        g_per_node[n] = pn;
    }
}

// ---------------------------------------------------------------------------
// K3: broadcast per_node over 3072 rows. 8 x STG.128 per thread.
// grid = 768 x 256.
// ---------------------------------------------------------------------------
__global__ __launch_bounds__(256) void k_broadcast(float4* __restrict__ out)
{
    const int c  = (blockIdx.x & 1) * 256 + threadIdx.x;  // f4 column 0..511
    const int r0 = (blockIdx.x >> 1) * 8;                 // row group of 8
    const float4 v = __ldg(reinterpret_cast<const float4*>(g_per_node) + c);
    float4* o = out + (size_t)r0 * NF4 + c;
    #pragma unroll
    for (int i = 0; i < 8; i++)
        o[(size_t)i * NF4] = v;
}

// ---------------------------------------------------------------------------
// Inputs: 0:x 1:edge_index(unused) 2:edge_attr(unused) 3:Wc 4:bc 5:W1 6:b1 7:W2 8:b2
// ---------------------------------------------------------------------------
extern "C" void kernel_launch(void* const* d_in, const int* in_sizes, int n_in,
                              void* d_out, int out_size)
{
    const float4* x4 = (const float4*)d_in[0];
    const float*  Wc = (const float*)d_in[3];
    const float*  bc = (const float*)d_in[4];
    const float*  W1 = (const float*)d_in[5];
    const float*  b1 = (const float*)d_in[6];
    const float*  W2 = (const float*)d_in[7];
    const float*  b2 = (const float*)d_in[8];
    float* out = (float*)d_out;

    k_gemm_partial<<<dim3(NBN, NKC), 256>>>(x4, Wc);
    k_reduce_mlp<<<32, 256>>>(bc, W1, b1, W2, b2);
    k_broadcast<<<768, 256>>>(reinterpret_cast<float4*>(out));
}

// round 9
// speedup vs baseline: 1.0031x; 1.0031x over previous
#include <cuda_runtime.h>
#include <cstdint>

// Problem constants
#define N_NODES 2048
#define NF4     512             // N_NODES/4 float4 columns
#define K_TOTAL 3072            // B*L
#define KC      128             // k rows per block
#define NKC     24              // k chunks (KC*NKC == K_TOTAL)
#define NBN     8               // n blocks (64 f4 cols each)
#define ROWS    3072

// Scratch device globals (no allocation allowed). Fully overwritten each launch.
__device__ float g_part[NKC * 8 * N_NODES];   // 1.5 MB partial conv sums
__device__ float g_per_node[N_NODES];         // 8 KB per-node scalars

// ---- helpers ---------------------------------------------------------------
// evict_last policy register (createpolicy + cache_hint works for v4.f32).
__device__ __forceinline__ unsigned long long mk_keep_policy() {
    unsigned long long pol;
    asm("createpolicy.fractional.L2::evict_last.b64 %0, 1.0;" : "=l"(pol));
    return pol;
}
__device__ __forceinline__ float4 ldg4_keep(const float4* p, unsigned long long pol) {
    float4 v;
    asm volatile("ld.global.nc.L2::cache_hint.v4.f32 {%0,%1,%2,%3}, [%4], %5;"
                 : "=f"(v.x), "=f"(v.y), "=f"(v.z), "=f"(v.w)
                 : "l"(p), "l"(pol));
    return v;
}
// partial reads: evict-first (single use)
__device__ __forceinline__ float ldg1_stream(const float* p) {
    float v;
    asm volatile("ld.global.cs.f32 %0, [%1];" : "=f"(v) : "l"(p));
    return v;
}
__device__ __forceinline__ unsigned long long pack2(float a, float b) {
    unsigned long long r;
    asm("mov.b64 %0, {%1, %2};" : "=l"(r) : "f"(a), "f"(b));
    return r;
}
__device__ __forceinline__ void fma2v(unsigned long long& d,
                                      unsigned long long a,
                                      unsigned long long b) {
    asm volatile("fma.rn.f32x2 %0, %1, %2, %0;" : "+l"(d) : "l"(a), "l"(b));
}
__device__ __forceinline__ void unpack2(unsigned long long v, float& a, float& b) {
    asm("mov.b64 {%0, %1}, %2;" : "=f"(a), "=f"(b) : "l"(v));
}

// ---------------------------------------------------------------------------
// K1: partial skinny GEMM (R4 structure). Block = 64 f4-cols x 4 k-quarters
// (KC=128 rows). Thread: one f4 column over 32 k-rows, forced 8-deep batches,
// x loads pinned in L2 via evict_last policy. grid = (8,24) x 256.
// ---------------------------------------------------------------------------
__global__ __launch_bounds__(256, 2) void k_gemm_partial(
    const float4* __restrict__ x4, const float* __restrict__ Wc)
{
    __shared__ alignas(16) float sWd[KC * 8 * 2];    // 8 KB: Wc dup'd pairs
    __shared__ float4 sred[3 * 64 * 8];              // 24 KB: quarter partials

    const int tid  = threadIdx.x;
    const int ln   = tid & 63;
    const int q    = tid >> 6;
    const int nblk = blockIdx.x;
    const int kblk = blockIdx.y;

    const float* wsrc = Wc + (size_t)kblk * KC * 8;
    #pragma unroll
    for (int i = tid; i < KC * 8 * 2; i += 256) sWd[i] = wsrc[i >> 1];
    __syncthreads();

    const unsigned long long pol = mk_keep_policy();
    const int c  = nblk * 64 + ln;
    const int kq = q * 32;
    const float4* xp = x4 + ((size_t)kblk * KC + kq) * NF4 + c;
    const ulonglong2* wp =
        reinterpret_cast<const ulonglong2*>(sWd) + (size_t)kq * 4;

    unsigned long long accp[2][8];
    #pragma unroll
    for (int p = 0; p < 2; p++)
        #pragma unroll
        for (int j = 0; j < 8; j++) accp[p][j] = 0ull;

    #pragma unroll
    for (int kk = 0; kk < 32; kk += 8) {
        float4 xv[8];
        #pragma unroll
        for (int u = 0; u < 8; u++)              // 8 LDG.128 back-to-back
            xv[u] = ldg4_keep(xp + (size_t)(kk + u) * NF4, pol);
        #pragma unroll
        for (int u = 0; u < 8; u++) {
            unsigned long long lo = pack2(xv[u].x, xv[u].y);
            unsigned long long hi = pack2(xv[u].z, xv[u].w);
            const ulonglong2* w = wp + (kk + u) * 4;
            #pragma unroll
            for (int jj = 0; jj < 4; jj++) {
                ulonglong2 wv = w[jj];           // LDS.128: two j weights
                fma2v(accp[0][2 * jj],     lo, wv.x);
                fma2v(accp[1][2 * jj],     hi, wv.x);
                fma2v(accp[0][2 * jj + 1], lo, wv.y);
                fma2v(accp[1][2 * jj + 1], hi, wv.y);
            }
        }
    }

    if (q != 0) {
        float4* dst = sred + (size_t)(q - 1) * 64 * 8 + ln * 8;
        #pragma unroll
        for (int j = 0; j < 8; j++) {
            float4 o;
            unpack2(accp[0][j], o.x, o.y);
            unpack2(accp[1][j], o.z, o.w);
            dst[j] = o;
        }
    }
    __syncthreads();
    if (q == 0) {
        float4* gp4 = reinterpret_cast<float4*>(g_part);
        #pragma unroll
        for (int j = 0; j < 8; j++) {
            float4 o;
            unpack2(accp[0][j], o.x, o.y);
            unpack2(accp[1][j], o.z, o.w);
            #pragma unroll
            for (int s = 0; s < 3; s++) {
                float4 r = sred[(size_t)s * 64 * 8 + ln * 8 + j];
                o.x += r.x; o.y += r.y; o.z += r.z; o.w += r.w;
            }
            __stcs(gp4 + (size_t)(kblk * 8 + j) * NF4 + c, o);   // evict-first
        }
    }
}

// ---------------------------------------------------------------------------
// K2: reduce 24 partials per (n,j), add bc, folded MLP, write per_node[n].
// grid = 32 x 256; block = 64 nodes x 4 k-slices (6 chunks each).
// ---------------------------------------------------------------------------
__global__ __launch_bounds__(256) void k_reduce_mlp(
    const float* __restrict__ bc, const float* __restrict__ W1,
    const float* __restrict__ b1, const float* __restrict__ W2,
    const float* __restrict__ b2)
{
    __shared__ float sWeff[256];
    __shared__ float sb1[32];
    __shared__ float sW2v[32];
    __shared__ float sred[3 * 64 * 9];

    const int tid = threadIdx.x;
    const int ln  = tid & 63;
    const int q   = tid >> 6;
    const int n   = blockIdx.x * 64 + ln;

    sWeff[tid] = W1[tid] + W1[tid + 256];
    if (tid < 32) { sb1[tid] = b1[tid]; sW2v[tid] = W2[tid]; }

    float conv[8];
    #pragma unroll
    for (int j = 0; j < 8; j++) conv[j] = 0.0f;

    const int kc0 = q * 6;
    #pragma unroll
    for (int kc = kc0; kc < kc0 + 6; kc++) {
        const float* p = g_part + (size_t)(kc * 8) * N_NODES + n;
        float v[8];
        #pragma unroll
        for (int j = 0; j < 8; j++)
            v[j] = ldg1_stream(p + (size_t)j * N_NODES);
        #pragma unroll
        for (int j = 0; j < 8; j++) conv[j] += v[j];
    }

    if (q != 0) {
        #pragma unroll
        for (int j = 0; j < 8; j++)
            sred[(size_t)(q - 1) * 64 * 9 + ln * 9 + j] = conv[j];
    }
    __syncthreads();
    if (q == 0) {
        #pragma unroll
        for (int j = 0; j < 8; j++) {
            #pragma unroll
            for (int s = 0; s < 3; s++)
                conv[j] += sred[(size_t)s * 64 * 9 + ln * 9 + j];
            conv[j] += __ldg(bc + j);
        }

        float pn = __ldg(b2);
        #pragma unroll 4
        for (int m = 0; m < 32; m++) {
            float h = sb1[m];
            #pragma unroll
            for (int j = 0; j < 8; j++)
                h = fmaf(conv[j], sWeff[j * 32 + m], h);
            h = fmaxf(h, 0.01f * h);    // leaky_relu
            pn = fmaf(h, sW2v[m], pn);
        }
        g_per_node[n] = pn;
    }
}

// ---------------------------------------------------------------------------
// K3: broadcast per_node over 3072 rows. 8 x STG.128 evict-first per thread
// so the 25MB output stream does not evict x from L2. grid = 768 x 256.
// ---------------------------------------------------------------------------
__global__ __launch_bounds__(256) void k_broadcast(float4* __restrict__ out)
{
    const int c  = (blockIdx.x & 1) * 256 + threadIdx.x;  // f4 column 0..511
    const int r0 = (blockIdx.x >> 1) * 8;                 // row group of 8
    const float4 v = __ldg(reinterpret_cast<const float4*>(g_per_node) + c);
    float4* o = out + (size_t)r0 * NF4 + c;
    #pragma unroll
    for (int i = 0; i < 8; i++)
        __stcs(o + (size_t)i * NF4, v);
}

// ---------------------------------------------------------------------------
// Inputs: 0:x 1:edge_index(unused) 2:edge_attr(unused) 3:Wc 4:bc 5:W1 6:b1 7:W2 8:b2
// ---------------------------------------------------------------------------
extern "C" void kernel_launch(void* const* d_in, const int* in_sizes, int n_in,
                              void* d_out, int out_size)
{
    const float4* x4 = (const float4*)d_in[0];
    const float*  Wc = (const float*)d_in[3];
    const float*  bc = (const float*)d_in[4];
    const float*  W1 = (const float*)d_in[5];
    const float*  b1 = (const float*)d_in[6];
    const float*  W2 = (const float*)d_in[7];
    const float*  b2 = (const float*)d_in[8];
    float* out = (float*)d_out;

    k_gemm_partial<<<dim3(NBN, NKC), 256>>>(x4, Wc);
    k_reduce_mlp<<<32, 256>>>(bc, W1, b1, W2, b2);
    k_broadcast<<<768, 256>>>(reinterpret_cast<float4*>(out));
}